// round 7
// baseline (speedup 1.0000x reference)
#include <cuda_runtime.h>

// Correlation: out[b, di*9+dj, y, x] = (1/64) * sum_c f1[b,c,y,x] * f2pad[b,c,y+di,x+dj]
// f1,f2: [4,64,192,448] f32; out: [4,81,192,448] f32; D=4.
//
// R3 structure (119us champion): block (8,4,9)=288 thr, thread owns 4 x-pixels +
// one di row => 36 acc; cp.async 4-deep ring, CS=4 channels/stage, 1 barrier/stage.
// R7 deltas: (1) prefetch issued right after the barrier (full-stage overlap),
//            (2) f1 quads for the whole stage preloaded into regs after the barrier.

#define D    4
#define CC   64
#define HH   192
#define WW   448
#define BB   4
#define XT   32
#define YT   4
#define XPT  4
#define NTX  8
#define NDJ  9
#define NDI  9
#define PW   (XT + 2*D)      // 40
#define PH   (YT + 2*D)      // 12
#define CS   4               // channels per stage
#define NSTAGE (CC / CS)     // 16
#define NTHREADS (NTX * YT * NDI)  // 288
#define RING 4

#define F2_STAGE_FLOATS (CS*PH*PW)     // 1920
#define F1_STAGE_FLOATS (CS*YT*XT)     // 512
#define STAGE_FLOATS    (F2_STAGE_FLOATS + F1_STAGE_FLOATS)  // 2432
#define STAGE_BYTES     (STAGE_FLOATS * 4)                   // 9728

#define NCH_F2 (CS*PH*(PW/4))   // 480 16B chunks
#define NCH_F1 (CS*YT*(XT/4))   // 128 16B chunks
#define NCH    (NCH_F2 + NCH_F1) // 608
#define CSTRIDE_BYTES ((size_t)CS * HH * WW * 4)

__device__ __forceinline__ void cp_async16(unsigned saddr, const void* gaddr, int sz) {
    asm volatile("cp.async.cg.shared.global [%0], [%1], 16, %2;"
                 :: "r"(saddr), "l"(gaddr), "r"(sz));
}

__global__ __launch_bounds__(NTHREADS, 3)
void corr_kernel(const float* __restrict__ f1,
                 const float* __restrict__ f2,
                 float* __restrict__ out)
{
    __shared__ float smem[RING * STAGE_FLOATS];   // 38912 B

    const int tx  = threadIdx.x;   // 0..7
    const int ty  = threadIdx.y;   // 0..3
    const int di  = threadIdx.z;   // 0..8
    const int tid = (di * YT + ty) * NTX + tx;

    const int x0 = blockIdx.x * XT;
    const int y0 = blockIdx.y * YT;
    const int b  = blockIdx.z;
    const int y  = y0 + ty;
    const int xp = tx * XPT;

    const float* f1b0 = f1 + (size_t)b * CC * HH * WW;
    const float* f2b0 = f2 + (size_t)b * CC * HH * WW;

    const unsigned sbase = (unsigned)__cvta_generic_to_shared(smem);

    // ---- precompute this thread's cp.async chunks (2 for all, 3rd for tid<32) ----
    const char* ckp[2];
    unsigned    cks[2];
    int         ckz[2];
#pragma unroll
    for (int k = 0; k < 2; k++) {
        const int c = tid + k * NTHREADS;   // < 608 always
        if (c < NCH_F2) {
            const int cc = c / (PH * (PW/4));
            const int rem = c - cc * (PH * (PW/4));
            const int r  = rem / (PW/4);
            const int h  = rem - r * (PW/4);
            const int gy  = y0 - D + r;
            const int gxf = x0 - D + h * 4;
            const bool ok = ((unsigned)gy < HH) && ((unsigned)gxf < WW);
            ckp[k] = (const char*)(f2b0 + (size_t)cc * HH * WW
                                  + (ok ? ((size_t)gy * WW + gxf) : 0));
            ckz[k] = ok ? 16 : 0;
            cks[k] = ((cc * PH + r) * PW + h * 4) * 4;
        } else {
            const int c2 = c - NCH_F2;
            const int cc = c2 / (YT * (XT/4));
            const int rem = c2 - cc * (YT * (XT/4));
            const int r  = rem / (XT/4);
            const int h  = rem - r * (XT/4);
            ckp[k] = (const char*)(f1b0 + (size_t)cc * HH * WW
                                  + (size_t)(y0 + r) * WW + x0 + h * 4);
            ckz[k] = 16;
            cks[k] = F2_STAGE_FLOATS * 4 + ((cc * YT + r) * XT + h * 4) * 4;
        }
    }
    const bool has3 = (tid < NCH - 2 * NTHREADS);   // tid < 32
    const char* ck3p = nullptr; unsigned ck3s = 0;
    if (has3) {
        const int c  = tid + 2 * NTHREADS;    // 576..607 -> f1 region
        const int c2 = c - NCH_F2;            // 96..127
        const int cc = c2 / (YT * (XT/4));
        const int rem = c2 - cc * (YT * (XT/4));
        const int r  = rem / (XT/4);
        const int h  = rem - r * (XT/4);
        ck3p = (const char*)(f1b0 + (size_t)cc * HH * WW
                             + (size_t)(y0 + r) * WW + x0 + h * 4);
        ck3s = F2_STAGE_FLOATS * 4 + ((cc * YT + r) * XT + h * 4) * 4;
    }

    auto prefetch = [&](int s) {
        if (s < NSTAGE) {
            const size_t gadd = (size_t)s * CSTRIDE_BYTES;
            const unsigned sb = sbase + (s & (RING - 1)) * STAGE_BYTES;
            cp_async16(sb + cks[0], ckp[0] + gadd, ckz[0]);
            cp_async16(sb + cks[1], ckp[1] + gadd, ckz[1]);
            if (has3) cp_async16(sb + ck3s, ck3p + gadd, 16);
        }
        asm volatile("cp.async.commit_group;" ::: "memory");
    };

    float acc[NDJ][XPT];
#pragma unroll
    for (int dj = 0; dj < NDJ; dj++)
#pragma unroll
        for (int xx = 0; xx < XPT; xx++) acc[dj][xx] = 0.f;

    prefetch(0);
    prefetch(1);
    prefetch(2);

#pragma unroll 4
    for (int s = 0; s < NSTAGE; s++) {
        asm volatile("cp.async.wait_group 2;" ::: "memory");
        __syncthreads();

        // Early prefetch: stage s+3 lands in buffer (s-1)&3, which every thread
        // finished reading before passing the barrier above.
        prefetch(s + 3);

        const float* f2t = smem + (s & (RING - 1)) * STAGE_FLOATS;
        const float* f1t = f2t + F2_STAGE_FLOATS;

        // Stage-level f1 preload: 4 channels x 4 pixels into registers,
        // issued back-to-back for MLP; inner loop is window-LDS -> FMA only.
        float4 v1s[CS];
#pragma unroll
        for (int cc = 0; cc < CS; cc++)
            v1s[cc] = *(const float4*)&f1t[(cc * YT + ty) * XT + xp];

#pragma unroll
        for (int cc = 0; cc < CS; cc++) {
            const float4 v1 = v1s[cc];
            const float* wrow = &f2t[(cc * PH + ty + di) * PW + xp];
            float w[12];
            *(float4*)&w[0] = *(const float4*)&wrow[0];
            *(float4*)&w[4] = *(const float4*)&wrow[4];
            *(float4*)&w[8] = *(const float4*)&wrow[8];
#pragma unroll
            for (int dj = 0; dj < NDJ; dj++) {
                acc[dj][0] += v1.x * w[dj + 0];
                acc[dj][1] += v1.y * w[dj + 1];
                acc[dj][2] += v1.z * w[dj + 2];
                acc[dj][3] += v1.w * w[dj + 3];
            }
        }
    }

    const float scale = 1.f / (float)CC;
    float* ob = out + (((size_t)b * (NDI * NDJ) + di * NDJ) * HH + y) * WW + x0 + xp;
#pragma unroll
    for (int dj = 0; dj < NDJ; dj++) {
        float4 o;
        o.x = acc[dj][0] * scale;
        o.y = acc[dj][1] * scale;
        o.z = acc[dj][2] * scale;
        o.w = acc[dj][3] * scale;
        *(float4*)&ob[(size_t)dj * HH * WW] = o;
    }
}

extern "C" void kernel_launch(void* const* d_in, const int* in_sizes, int n_in,
                              void* d_out, int out_size)
{
    const float* f1 = (const float*)d_in[0];
    const float* f2 = (const float*)d_in[1];
    float* out = (float*)d_out;

    dim3 grid(WW / XT, HH / YT, BB);   // 14 x 48 x 4 = 2688 CTAs
    dim3 block(NTX, YT, NDI);          // 288 threads
    corr_kernel<<<grid, block>>>(f1, f2, out);
}

// round 8
// speedup vs baseline: 1.1062x; 1.1062x over previous
#include <cuda_runtime.h>

// Correlation: out[b, di*9+dj, y, x] = (1/64) * sum_c f1[b,c,y,x] * f2pad[b,c,y+di,x+dj]
// f1,f2: [4,64,192,448] f32; out: [4,81,192,448] f32; D=4.
//
// R3 champion structure (119us): block (8,4,9)=288 thr, thread owns 4 x-pixels +
// one di row => 36 acc; cp.async 4-deep ring, CS=4 channels/stage, 1 barrier/stage,
// prefetch issued at END of compute (measured best). This round: FULL unroll of the
// 16-stage loop so ring-buffer offsets become immediates (fewer IMADs, cross-stage
// scheduling).

#define D    4
#define CC   64
#define HH   192
#define WW   448
#define BB   4
#define XT   32
#define YT   4
#define XPT  4
#define NTX  8
#define NDJ  9
#define NDI  9
#define PW   (XT + 2*D)      // 40
#define PH   (YT + 2*D)      // 12
#define CS   4               // channels per stage
#define NSTAGE (CC / CS)     // 16
#define NTHREADS (NTX * YT * NDI)  // 288
#define RING 4

#define F2_STAGE_FLOATS (CS*PH*PW)     // 1920
#define F1_STAGE_FLOATS (CS*YT*XT)     // 512
#define STAGE_FLOATS    (F2_STAGE_FLOATS + F1_STAGE_FLOATS)  // 2432
#define STAGE_BYTES     (STAGE_FLOATS * 4)                   // 9728

#define NCH_F2 (CS*PH*(PW/4))   // 480 16B chunks
#define NCH_F1 (CS*YT*(XT/4))   // 128 16B chunks
#define NCH    (NCH_F2 + NCH_F1) // 608
#define CSTRIDE_BYTES ((size_t)CS * HH * WW * 4)

__device__ __forceinline__ void cp_async16(unsigned saddr, const void* gaddr, int sz) {
    asm volatile("cp.async.cg.shared.global [%0], [%1], 16, %2;"
                 :: "r"(saddr), "l"(gaddr), "r"(sz));
}

__global__ __launch_bounds__(NTHREADS, 3)
void corr_kernel(const float* __restrict__ f1,
                 const float* __restrict__ f2,
                 float* __restrict__ out)
{
    __shared__ float smem[RING * STAGE_FLOATS];   // 38912 B

    const int tx  = threadIdx.x;   // 0..7
    const int ty  = threadIdx.y;   // 0..3
    const int di  = threadIdx.z;   // 0..8
    const int tid = (di * YT + ty) * NTX + tx;

    const int x0 = blockIdx.x * XT;
    const int y0 = blockIdx.y * YT;
    const int b  = blockIdx.z;
    const int y  = y0 + ty;
    const int xp = tx * XPT;

    const float* f1b0 = f1 + (size_t)b * CC * HH * WW;
    const float* f2b0 = f2 + (size_t)b * CC * HH * WW;

    const unsigned sbase = (unsigned)__cvta_generic_to_shared(smem);

    // ---- precompute this thread's cp.async chunks (2 for all, 3rd for tid<32) ----
    const char* ckp[2];
    unsigned    cks[2];
    int         ckz[2];
#pragma unroll
    for (int k = 0; k < 2; k++) {
        const int c = tid + k * NTHREADS;   // < 608 always
        if (c < NCH_F2) {
            const int cc = c / (PH * (PW/4));
            const int rem = c - cc * (PH * (PW/4));
            const int r  = rem / (PW/4);
            const int h  = rem - r * (PW/4);
            const int gy  = y0 - D + r;
            const int gxf = x0 - D + h * 4;
            const bool ok = ((unsigned)gy < HH) && ((unsigned)gxf < WW);
            ckp[k] = (const char*)(f2b0 + (size_t)cc * HH * WW
                                  + (ok ? ((size_t)gy * WW + gxf) : 0));
            ckz[k] = ok ? 16 : 0;
            cks[k] = ((cc * PH + r) * PW + h * 4) * 4;
        } else {
            const int c2 = c - NCH_F2;
            const int cc = c2 / (YT * (XT/4));
            const int rem = c2 - cc * (YT * (XT/4));
            const int r  = rem / (XT/4);
            const int h  = rem - r * (XT/4);
            ckp[k] = (const char*)(f1b0 + (size_t)cc * HH * WW
                                  + (size_t)(y0 + r) * WW + x0 + h * 4);
            ckz[k] = 16;
            cks[k] = F2_STAGE_FLOATS * 4 + ((cc * YT + r) * XT + h * 4) * 4;
        }
    }
    const bool has3 = (tid < NCH - 2 * NTHREADS);   // tid < 32
    const char* ck3p = nullptr; unsigned ck3s = 0;
    if (has3) {
        const int c  = tid + 2 * NTHREADS;    // 576..607 -> f1 region
        const int c2 = c - NCH_F2;            // 96..127
        const int cc = c2 / (YT * (XT/4));
        const int rem = c2 - cc * (YT * (XT/4));
        const int r  = rem / (XT/4);
        const int h  = rem - r * (XT/4);
        ck3p = (const char*)(f1b0 + (size_t)cc * HH * WW
                             + (size_t)(y0 + r) * WW + x0 + h * 4);
        ck3s = F2_STAGE_FLOATS * 4 + ((cc * YT + r) * XT + h * 4) * 4;
    }

    auto prefetch = [&](int s) {
        if (s < NSTAGE) {
            const size_t gadd = (size_t)s * CSTRIDE_BYTES;
            const unsigned sb = sbase + (s & (RING - 1)) * STAGE_BYTES;
            cp_async16(sb + cks[0], ckp[0] + gadd, ckz[0]);
            cp_async16(sb + cks[1], ckp[1] + gadd, ckz[1]);
            if (has3) cp_async16(sb + ck3s, ck3p + gadd, 16);
        }
        asm volatile("cp.async.commit_group;" ::: "memory");
    };

    float acc[NDJ][XPT];
#pragma unroll
    for (int dj = 0; dj < NDJ; dj++)
#pragma unroll
        for (int xx = 0; xx < XPT; xx++) acc[dj][xx] = 0.f;

    prefetch(0);
    prefetch(1);
    prefetch(2);

#pragma unroll
    for (int s = 0; s < NSTAGE; s++) {
        asm volatile("cp.async.wait_group 2;" ::: "memory");
        __syncthreads();

        const float* f2t = smem + (s & (RING - 1)) * STAGE_FLOATS;
        const float* f1t = f2t + F2_STAGE_FLOATS;

#pragma unroll
        for (int cc = 0; cc < CS; cc++) {
            const float4 v1 = *(const float4*)&f1t[(cc * YT + ty) * XT + xp];
            const float* wrow = &f2t[(cc * PH + ty + di) * PW + xp];
            float w[12];
            *(float4*)&w[0] = *(const float4*)&wrow[0];
            *(float4*)&w[4] = *(const float4*)&wrow[4];
            *(float4*)&w[8] = *(const float4*)&wrow[8];
#pragma unroll
            for (int dj = 0; dj < NDJ; dj++) {
                acc[dj][0] += v1.x * w[dj + 0];
                acc[dj][1] += v1.y * w[dj + 1];
                acc[dj][2] += v1.z * w[dj + 2];
                acc[dj][3] += v1.w * w[dj + 3];
            }
        }
        // Prefetch at END of compute (measured best in R3/R7 A/B): stage s+3
        // lands in buffer (s-1)&3, fully consumed before this stage's barrier.
        prefetch(s + 3);
    }

    const float scale = 1.f / (float)CC;
    float* ob = out + (((size_t)b * (NDI * NDJ) + di * NDJ) * HH + y) * WW + x0 + xp;
#pragma unroll
    for (int dj = 0; dj < NDJ; dj++) {
        float4 o;
        o.x = acc[dj][0] * scale;
        o.y = acc[dj][1] * scale;
        o.z = acc[dj][2] * scale;
        o.w = acc[dj][3] * scale;
        *(float4*)&ob[(size_t)dj * HH * WW] = o;
    }
}

extern "C" void kernel_launch(void* const* d_in, const int* in_sizes, int n_in,
                              void* d_out, int out_size)
{
    const float* f1 = (const float*)d_in[0];
    const float* f2 = (const float*)d_in[1];
    float* out = (float*)d_out;

    dim3 grid(WW / XT, HH / YT, BB);   // 14 x 48 x 4 = 2688 CTAs
    dim3 block(NTX, YT, NDI);          // 288 threads
    corr_kernel<<<grid, block>>>(f1, f2, out);
}